// round 5
// baseline (speedup 1.0000x reference)
#include <cuda_runtime.h>
#include <math.h>
#include <stdint.h>

#define NN   8192
#define FIN  256
#define NH   4
#define ND   64
#define HD   256
#define LDW  68
#define LDB  68

// ---------------- device scratch (allocation-free contract) ----------------
__device__ float g_hT [NH * ND * NN];     // projected features, exact: [h][d][n]
__device__ float g_hB [NH * ND * NN];     // projected features, tf32-rounded
__device__ float g_nsl[NH * NN];
__device__ float g_el [NH * NN];
__device__ float g_el2[NH * NN];
__device__ float g_sr [NH * NN];
__device__ float g_er [NH * NN];
__device__ float g_er2[NH * NN];
__device__ unsigned int g_keep[NN * 256 + 512];   // keep bitmask, diag folded

// ---------------- helpers ----------------
__device__ __forceinline__ float tf32r(float x) {
    unsigned int u;
    asm("cvt.rna.tf32.f32 %0, %1;" : "=r"(u) : "f"(x));
    return __uint_as_float(u);
}
__device__ __forceinline__ void ldsm4(unsigned int* r, unsigned int addr) {
    asm volatile("ldmatrix.sync.aligned.m8n8.x4.shared.b16 {%0,%1,%2,%3}, [%4];"
                 : "=r"(r[0]), "=r"(r[1]), "=r"(r[2]), "=r"(r[3]) : "r"(addr));
}
__device__ __forceinline__ void mma_tf32(float* c, const unsigned int* a,
                                         unsigned int b0, unsigned int b1) {
    asm volatile("mma.sync.aligned.m16n8k8.row.col.f32.tf32.tf32.f32 "
                 "{%0,%1,%2,%3}, {%4,%5,%6,%7}, {%8,%9}, {%0,%1,%2,%3};"
                 : "+f"(c[0]), "+f"(c[1]), "+f"(c[2]), "+f"(c[3])
                 : "r"(a[0]), "r"(a[1]), "r"(a[2]), "r"(a[3]), "r"(b0), "r"(b1));
}

// ---------------- Kernel 1: g_hT/g_hB = (x @ W)^T ----------------
__global__ __launch_bounds__(256) void k_proj(const float* __restrict__ A,
                                              const float* __restrict__ B) {
    __shared__ float As[64 * 17];
    __shared__ float Bs[16 * 64];
    __shared__ float Tb[64 * 68];
    const int t  = threadIdx.x;
    const int ty = t >> 4, tx = t & 15;
    const int row0 = blockIdx.y * 64, col0 = blockIdx.x * 64;
    float acc[4][4] = {};
    for (int k0 = 0; k0 < FIN; k0 += 16) {
        #pragma unroll
        for (int l = 0; l < 4; ++l) {
            int idx = t + l * 256;
            int m = idx >> 4, k = idx & 15;
            As[m * 17 + k] = A[(size_t)(row0 + m) * FIN + k0 + k];
            int kb = idx >> 6, n = idx & 63;
            Bs[kb * 64 + n] = B[(size_t)(k0 + kb) * HD + col0 + n];
        }
        __syncthreads();
        #pragma unroll
        for (int k = 0; k < 16; ++k) {
            float a0 = As[(ty * 4 + 0) * 17 + k];
            float a1 = As[(ty * 4 + 1) * 17 + k];
            float a2 = As[(ty * 4 + 2) * 17 + k];
            float a3 = As[(ty * 4 + 3) * 17 + k];
            float4 b = *(const float4*)&Bs[k * 64 + tx * 4];
            acc[0][0] += a0 * b.x; acc[0][1] += a0 * b.y; acc[0][2] += a0 * b.z; acc[0][3] += a0 * b.w;
            acc[1][0] += a1 * b.x; acc[1][1] += a1 * b.y; acc[1][2] += a1 * b.z; acc[1][3] += a1 * b.w;
            acc[2][0] += a2 * b.x; acc[2][1] += a2 * b.y; acc[2][2] += a2 * b.z; acc[2][3] += a2 * b.w;
            acc[3][0] += a3 * b.x; acc[3][1] += a3 * b.y; acc[3][2] += a3 * b.z; acc[3][3] += a3 * b.w;
        }
        __syncthreads();
    }
    #pragma unroll
    for (int i = 0; i < 4; ++i)
        #pragma unroll
        for (int j = 0; j < 4; ++j)
            Tb[(tx * 4 + j) * 68 + (ty * 4 + i)] = acc[i][j];
    __syncthreads();
    const int c = t >> 2, q = t & 3;
    #pragma unroll
    for (int m = 0; m < 4; ++m) {
        float4 v = *(const float4*)&Tb[c * 68 + q * 16 + m * 4];
        size_t go = (size_t)(col0 + c) * NN + row0 + q * 16 + m * 4;
        *(float4*)(g_hT + go) = v;
        float4 r = make_float4(tf32r(v.x), tf32r(v.y), tf32r(v.z), tf32r(v.w));
        *(float4*)(g_hB + go) = r;
    }
}

// ---------------- Kernel 2: per-(node, head) scores + exp factors ----------------
__global__ __launch_bounds__(256) void k_scores(const float* __restrict__ a_l,
                                                const float* __restrict__ a_r) {
    __shared__ float alS[HD], arS[HD];
    const int t = threadIdx.x;
    if (t < HD) { alS[t] = a_l[t]; arS[t] = a_r[t]; }
    __syncthreads();
    const int n = blockIdx.x * 256 + t;
    #pragma unroll
    for (int h = 0; h < NH; ++h) {
        float sl = 0.f, sr = 0.f;
        #pragma unroll 8
        for (int d = 0; d < ND; ++d) {
            float v = g_hT[(size_t)(h * ND + d) * NN + n];
            sl += v * alS[h * ND + d];
            sr += v * arS[h * ND + d];
        }
        const int idx = h * NN + n;
        g_nsl[idx] = -sl;
        g_el [idx] = expf(sl);
        g_el2[idx] = expf(0.2f * sl);
        g_sr [idx] = sr;
        g_er [idx] = expf(sr);
        g_er2[idx] = expf(0.2f * sr);
    }
}

// ---------------- Kernel 2b: pack (adj + eye) != 0 into bitmask ----------------
__global__ __launch_bounds__(256) void k_pack(const int* __restrict__ adj) {
    const int gid  = blockIdx.x * 256 + threadIdx.x;
    const int lane = gid & 31;
    const int w0   = gid >> 5;
    const int nw   = (gridDim.x * 256) >> 5;
    for (int t = w0; t < NN * 256; t += nw) {
        const int row = t >> 8;
        const int w   = t & 255;
        const int v = adj[(size_t)row * NN + w * 32 + lane];
        unsigned int word = __ballot_sync(0xffffffffu, v != 0);
        if (lane == 0) {
            if ((row >> 5) == w) word |= 1u << (row & 31);
            g_keep[t] = word;
        }
    }
}

// ---------------- Kernel 3: fused aggregation, bitmask + full prefetch ----------
#define WBUF   (128 * LDW)
#define BBUF   (64 * LDB)
#define OFF_BT (2 * WBUF)
#define OFF_NSL (OFF_BT + 2 * BBUF)
#define OFF_EL  (OFF_NSL + 128)
#define OFF_EL2 (OFF_EL + 128)
#define OFF_DN  (OFF_EL2 + 128)
#define OFF_IV  (OFF_DN + 128)
#define SMEM_FLOATS (OFF_IV + 128)
#define SMEM_BYTES  (SMEM_FLOATS * 4)

#define CHUNK(JT, BUF, KWC, SRC, ERC, ER2C, KWN, SRN, ERN, ER2N)               \
{                                                                              \
    const int j0 = (JT) * 64;                                                  \
    /* stage B tile (pre-rounded tf32) */                                      \
    {                                                                          \
        float* bufB = sm + OFF_BT + (BUF) * BBUF + bn * LDB + bq * 16;         \
        const float* hrow = hp + j0 + bq * 16;                                 \
        _Pragma("unroll")                                                      \
        for (int m = 0; m < 4; ++m)                                            \
            *(float4*)(bufB + m * 4) = *(const float4*)(hrow + m * 4);         \
    }                                                                          \
    /* weight generation from prefetched bits/factors */                       \
    {                                                                          \
        float* bufW = sm + (BUF) * WBUF + jj4 * 4;                             \
        _Pragma("unroll")                                                      \
        for (int k = 0; k < 8; ++k) {                                          \
            const unsigned int nib = (KWC)[k] >> shift;                        \
            const float nsl_i = nslS[k * 16 + ii];                             \
            const float el_i  = elS [k * 16 + ii];                             \
            const float el2_i = el2S[k * 16 + ii];                             \
            float s0 = (SRC.x > nsl_i) ? el_i * ERC.x : el2_i * ER2C.x;        \
            float s1 = (SRC.y > nsl_i) ? el_i * ERC.y : el2_i * ER2C.y;        \
            float s2 = (SRC.z > nsl_i) ? el_i * ERC.z : el2_i * ER2C.z;        \
            float s3 = (SRC.w > nsl_i) ? el_i * ERC.w : el2_i * ER2C.w;        \
            float w0 = (nib & 1u) ? s0 : 0.f;                                  \
            float w1 = (nib & 2u) ? s1 : 0.f;                                  \
            float w2 = (nib & 4u) ? s2 : 0.f;                                  \
            float w3 = (nib & 8u) ? s3 : 0.f;                                  \
            w0 = tf32r(w0); w1 = tf32r(w1); w2 = tf32r(w2); w3 = tf32r(w3);    \
            dpart[k] += (w0 + w1) + (w2 + w3);                                 \
            *(float4*)(bufW + (k * 16 + ii) * LDW) = make_float4(w0,w1,w2,w3); \
        }                                                                      \
    }                                                                          \
    __syncthreads();                                                           \
    /* prefetch next chunk's bits + factors (hidden behind MMA) */             \
    if ((JT) + 1 < 128) {                                                      \
        const int jn = j0 + 64;                                                \
        _Pragma("unroll")                                                      \
        for (int k = 0; k < 8; ++k)                                            \
            (KWN)[k] = keepB[k * 4096 + ((JT) + 1) * 2];                       \
        SRN  = *(const float4*)(srG  + jn + jj4 * 4);                          \
        ERN  = *(const float4*)(erG  + jn + jj4 * 4);                          \
        ER2N = *(const float4*)(er2G + jn + jj4 * 4);                          \
    }                                                                          \
    /* tensor-core accumulation */                                             \
    {                                                                          \
        const unsigned int aO = (BUF) ? (unsigned int)(WBUF * 4) : 0u;         \
        const unsigned int bO = (BUF) ? (unsigned int)(BBUF * 4) : 0u;         \
        _Pragma("unroll")                                                      \
        for (int kp = 0; kp < 4; ++kp) {                                       \
            unsigned int bf[4][4];                                             \
            _Pragma("unroll")                                                  \
            for (int nt = 0; nt < 4; ++nt) ldsm4(bf[nt], bAddr[nt] + bO + kp * 64); \
            _Pragma("unroll")                                                  \
            for (int sub = 0; sub < 2; ++sub) {                                \
                const int ks = kp * 2 + sub;                                   \
                unsigned int a0[4], a1[4];                                     \
                ldsm4(a0, aAddr0 + aO + ks * 32);                              \
                ldsm4(a1, aAddr1 + aO + ks * 32);                              \
                _Pragma("unroll")                                              \
                for (int nt = 0; nt < 4; ++nt) {                               \
                    mma_tf32(acc[0][nt], a0, bf[nt][2 * sub], bf[nt][2 * sub + 1]); \
                    mma_tf32(acc[1][nt], a1, bf[nt][2 * sub], bf[nt][2 * sub + 1]); \
                }                                                              \
            }                                                                  \
        }                                                                      \
    }                                                                          \
}

__global__ __launch_bounds__(256, 2) void k_gat(float* __restrict__ out) {
    extern __shared__ float sm[];
    float* nslS = sm + OFF_NSL;
    float* elS  = sm + OFF_EL;
    float* el2S = sm + OFF_EL2;
    float* denS = sm + OFF_DN;
    float* invD = sm + OFF_IV;

    const int tid  = threadIdx.x;
    const int lane = tid & 31;
    const int warp = tid >> 5;
    const int h    = blockIdx.x;
    const int i0   = blockIdx.y * 128;

    const int ii  = tid >> 4;       // 0..15
    const int jj4 = tid & 15;       // 0..15
    const unsigned int shift = (unsigned int)((jj4 & 7) * 4);

    // stage row factors to smem (broadcast reads later)
    if (tid < 128) {
        nslS[tid] = g_nsl[h * NN + i0 + tid];
        elS [tid] = g_el [h * NN + i0 + tid];
        el2S[tid] = g_el2[h * NN + i0 + tid];
    }

    // B staging mapping
    const int bn = tid >> 2;
    const int bq = tid & 3;
    const float* hp = g_hB + (size_t)(h * ND + bn) * NN;

    // mma mapping
    const int wm = warp >> 1;
    const int wn = warp & 1;
    unsigned int sbase = (unsigned int)__cvta_generic_to_shared(sm);
    const unsigned int aAddr0 = sbase + ((wm * 32 + (lane & 15)) * LDW + (lane >> 4) * 4) * 4;
    const unsigned int aAddr1 = aAddr0 + 16 * LDW * 4;
    unsigned int bAddr[4];
    #pragma unroll
    for (int nt = 0; nt < 4; ++nt)
        bAddr[nt] = sbase + OFF_BT * 4 +
                    ((wn * 32 + nt * 8 + (lane & 7)) * LDB + (lane >> 3) * 4) * 4;

    float acc[2][4][4];
    #pragma unroll
    for (int a = 0; a < 2; ++a)
        #pragma unroll
        for (int b = 0; b < 4; ++b)
            #pragma unroll
            for (int c = 0; c < 4; ++c) acc[a][b][c] = 0.f;
    float dpart[8] = {};

    const float* srG  = g_sr  + h * NN;
    const float* erG  = g_er  + h * NN;
    const float* er2G = g_er2 + h * NN;
    const unsigned int* keepB = g_keep + (size_t)(i0 + ii) * 256 + (jj4 >> 3);

    // prologue: prefetch chunk 0
    unsigned int kwA[8], kwB[8];
    float4 srA, erA, er2A, srB, erB, er2B;
    #pragma unroll
    for (int k = 0; k < 8; ++k) kwA[k] = keepB[k * 4096];
    srA  = *(const float4*)(srG  + jj4 * 4);
    erA  = *(const float4*)(erG  + jj4 * 4);
    er2A = *(const float4*)(er2G + jj4 * 4);
    __syncthreads();   // row factors visible

    for (int jt = 0; jt < 128; jt += 2) {
        CHUNK(jt,     0, kwA, srA, erA, er2A, kwB, srB, erB, er2B)
        CHUNK(jt + 1, 1, kwB, srB, erB, er2B, kwA, srA, erA, er2A)
    }

    // ---- denominators: 16-lane shuffle reduction ----
    #pragma unroll
    for (int k = 0; k < 8; ++k) {
        float v = dpart[k];
        v += __shfl_xor_sync(0xffffffffu, v, 1);
        v += __shfl_xor_sync(0xffffffffu, v, 2);
        v += __shfl_xor_sync(0xffffffffu, v, 4);
        v += __shfl_xor_sync(0xffffffffu, v, 8);
        if (jj4 == 0) denS[k * 16 + ii] = v;
    }
    __syncthreads();
    if (tid < 128) invD[tid] = 1.0f / denS[tid];
    __syncthreads();

    // ---- epilogue: normalize + store ----
    #pragma unroll
    for (int mt = 0; mt < 2; ++mt) {
        const int r0 = wm * 32 + mt * 16 + (lane >> 2);
        const float inv0 = invD[r0], inv1 = invD[r0 + 8];
        #pragma unroll
        for (int nt = 0; nt < 4; ++nt) {
            const int c = h * ND + wn * 32 + nt * 8 + (lane & 3) * 2;
            float2 v0 = make_float2(acc[mt][nt][0] * inv0, acc[mt][nt][1] * inv0);
            float2 v1 = make_float2(acc[mt][nt][2] * inv1, acc[mt][nt][3] * inv1);
            *(float2*)(out + (size_t)(i0 + r0)     * HD + c) = v0;
            *(float2*)(out + (size_t)(i0 + r0 + 8) * HD + c) = v1;
        }
    }
}

// ---------------- launch ----------------
extern "C" void kernel_launch(void* const* d_in, const int* in_sizes, int n_in,
                              void* d_out, int out_size) {
    const float* x   = (const float*)d_in[0];
    const int*   adj = (const int*)  d_in[1];
    const float* W   = (const float*)d_in[2];
    const float* a_l = (const float*)d_in[3];
    const float* a_r = (const float*)d_in[4];
    float* out = (float*)d_out;

    k_proj<<<dim3(HD / 64, NN / 64), 256>>>(x, W);
    k_scores<<<NN / 256, 256>>>(a_l, a_r);
    k_pack<<<2048, 256>>>(adj);

    cudaFuncSetAttribute(k_gat, cudaFuncAttributeMaxDynamicSharedMemorySize, SMEM_BYTES);
    k_gat<<<dim3(NH, NN / 128), 256, SMEM_BYTES>>>(out);
}

// round 6
// speedup vs baseline: 1.2409x; 1.2409x over previous
#include <cuda_runtime.h>
#include <math.h>
#include <stdint.h>

#define NN   8192
#define FIN  256
#define NH   4
#define ND   64
#define HD   256
#define LDW  68
#define LDB  68

// ---------------- device scratch (allocation-free contract) ----------------
__device__ float g_hT [NH * ND * NN];     // projected features, exact: [h][d][n]
__device__ float g_hB [NH * ND * NN];     // projected features, tf32-rounded
__device__ float g_nsl[NH * NN];          // -score_l
__device__ float g_q  [NH * NN];          // exp(0.8 * score_l)
__device__ float g_sr [NH * NN];
__device__ float g_er [NH * NN];
__device__ float g_er2[NH * NN];
__device__ unsigned int g_keep[NN * 256 + 512];   // keep bitmask, diag folded

// ---------------- helpers ----------------
__device__ __forceinline__ float tf32r(float x) {
    unsigned int u;
    asm("cvt.rna.tf32.f32 %0, %1;" : "=r"(u) : "f"(x));
    return __uint_as_float(u);
}
__device__ __forceinline__ void ldsm4(unsigned int* r, unsigned int addr) {
    asm volatile("ldmatrix.sync.aligned.m8n8.x4.shared.b16 {%0,%1,%2,%3}, [%4];"
                 : "=r"(r[0]), "=r"(r[1]), "=r"(r[2]), "=r"(r[3]) : "r"(addr));
}
__device__ __forceinline__ void mma_tf32(float* c, const unsigned int* a,
                                         unsigned int b0, unsigned int b1) {
    asm volatile("mma.sync.aligned.m16n8k8.row.col.f32.tf32.tf32.f32 "
                 "{%0,%1,%2,%3}, {%4,%5,%6,%7}, {%8,%9}, {%0,%1,%2,%3};"
                 : "+f"(c[0]), "+f"(c[1]), "+f"(c[2]), "+f"(c[3])
                 : "r"(a[0]), "r"(a[1]), "r"(a[2]), "r"(a[3]), "r"(b0), "r"(b1));
}

// ---------------- Kernel 1: g_hT/g_hB = (x @ W)^T ----------------
__global__ __launch_bounds__(256) void k_proj(const float* __restrict__ A,
                                              const float* __restrict__ B) {
    __shared__ float As[64 * 17];
    __shared__ float Bs[16 * 64];
    __shared__ float Tb[64 * 68];
    const int t  = threadIdx.x;
    const int ty = t >> 4, tx = t & 15;
    const int row0 = blockIdx.y * 64, col0 = blockIdx.x * 64;
    float acc[4][4] = {};
    for (int k0 = 0; k0 < FIN; k0 += 16) {
        #pragma unroll
        for (int l = 0; l < 4; ++l) {
            int idx = t + l * 256;
            int m = idx >> 4, k = idx & 15;
            As[m * 17 + k] = A[(size_t)(row0 + m) * FIN + k0 + k];
            int kb = idx >> 6, n = idx & 63;
            Bs[kb * 64 + n] = B[(size_t)(k0 + kb) * HD + col0 + n];
        }
        __syncthreads();
        #pragma unroll
        for (int k = 0; k < 16; ++k) {
            float a0 = As[(ty * 4 + 0) * 17 + k];
            float a1 = As[(ty * 4 + 1) * 17 + k];
            float a2 = As[(ty * 4 + 2) * 17 + k];
            float a3 = As[(ty * 4 + 3) * 17 + k];
            float4 b = *(const float4*)&Bs[k * 64 + tx * 4];
            acc[0][0] += a0 * b.x; acc[0][1] += a0 * b.y; acc[0][2] += a0 * b.z; acc[0][3] += a0 * b.w;
            acc[1][0] += a1 * b.x; acc[1][1] += a1 * b.y; acc[1][2] += a1 * b.z; acc[1][3] += a1 * b.w;
            acc[2][0] += a2 * b.x; acc[2][1] += a2 * b.y; acc[2][2] += a2 * b.z; acc[2][3] += a2 * b.w;
            acc[3][0] += a3 * b.x; acc[3][1] += a3 * b.y; acc[3][2] += a3 * b.z; acc[3][3] += a3 * b.w;
        }
        __syncthreads();
    }
    #pragma unroll
    for (int i = 0; i < 4; ++i)
        #pragma unroll
        for (int j = 0; j < 4; ++j)
            Tb[(tx * 4 + j) * 68 + (ty * 4 + i)] = acc[i][j];
    __syncthreads();
    const int c = t >> 2, q = t & 3;
    #pragma unroll
    for (int m = 0; m < 4; ++m) {
        float4 v = *(const float4*)&Tb[c * 68 + q * 16 + m * 4];
        size_t go = (size_t)(col0 + c) * NN + row0 + q * 16 + m * 4;
        *(float4*)(g_hT + go) = v;
        float4 r = make_float4(tf32r(v.x), tf32r(v.y), tf32r(v.z), tf32r(v.w));
        *(float4*)(g_hB + go) = r;
    }
}

// ---------------- Kernel 2: per-(node, head) scores + exp factors ----------------
__global__ __launch_bounds__(256) void k_scores(const float* __restrict__ a_l,
                                                const float* __restrict__ a_r) {
    __shared__ float alS[HD], arS[HD];
    const int t = threadIdx.x;
    if (t < HD) { alS[t] = a_l[t]; arS[t] = a_r[t]; }
    __syncthreads();
    const int n = blockIdx.x * 256 + t;
    #pragma unroll
    for (int h = 0; h < NH; ++h) {
        float sl = 0.f, sr = 0.f;
        #pragma unroll 8
        for (int d = 0; d < ND; ++d) {
            float v = g_hT[(size_t)(h * ND + d) * NN + n];
            sl += v * alS[h * ND + d];
            sr += v * arS[h * ND + d];
        }
        const int idx = h * NN + n;
        g_nsl[idx] = -sl;
        g_q  [idx] = expf(0.8f * sl);
        g_sr [idx] = sr;
        g_er [idx] = expf(sr);
        g_er2[idx] = expf(0.2f * sr);
    }
}

// ---------------- Kernel 2b: pack (adj + eye) != 0 into bitmask, MLP=8 ----------
__global__ __launch_bounds__(256) void k_pack(const int* __restrict__ adj) {
    const int lane = threadIdx.x & 31;
    const int gw   = (blockIdx.x * 256 + threadIdx.x) >> 5;
    const int nw   = (gridDim.x * 256) >> 5;
    for (int t = gw * 8; t < NN * 256; t += nw * 8) {
        const int* p = adj + (size_t)t * 32 + lane;
        int v[8];
        #pragma unroll
        for (int u = 0; u < 8; ++u) v[u] = p[u * 32];
        unsigned int b[8];
        #pragma unroll
        for (int u = 0; u < 8; ++u) b[u] = __ballot_sync(0xffffffffu, v[u] != 0);
        if (lane == 0) {
            #pragma unroll
            for (int u = 0; u < 8; ++u) {
                const int w = t + u, row = w >> 8, c = w & 255;
                if ((row >> 5) == c) b[u] |= 1u << (row & 31);
            }
            *(uint4*)(g_keep + t)     = make_uint4(b[0], b[1], b[2], b[3]);
            *(uint4*)(g_keep + t + 4) = make_uint4(b[4], b[5], b[6], b[7]);
        }
    }
}

// ---------------- Kernel 3: fused aggregation ----------------
#define WBUF   (128 * LDW)
#define BBUF   (64 * LDB)
#define OFF_BT (2 * WBUF)
#define OFF_DN (OFF_BT + 2 * BBUF)
#define OFF_IV (OFF_DN + 128)
#define SMEM_FLOATS (OFF_IV + 128)
#define SMEM_BYTES  (SMEM_FLOATS * 4)

#define CHUNK(JT, BUF, KWC, SRC, ERC, ER2C, KWN, SRN, ERN, ER2N)               \
{                                                                              \
    const int j0 = (JT) * 64;                                                  \
    /* stage B tile (pre-rounded tf32) */                                      \
    {                                                                          \
        float* bufB = sm + OFF_BT + (BUF) * BBUF + bn * LDB + bq * 16;         \
        const float* hrow = hp + j0 + bq * 16;                                 \
        _Pragma("unroll")                                                      \
        for (int m = 0; m < 4; ++m)                                            \
            *(float4*)(bufB + m * 4) = *(const float4*)(hrow + m * 4);         \
    }                                                                          \
    /* weight generation (row-factor-cancelled form) */                        \
    {                                                                          \
        float* bufW = sm + (BUF) * WBUF + jj4 * 4;                             \
        _Pragma("unroll")                                                      \
        for (int k = 0; k < 8; ++k) {                                          \
            const unsigned int nib = (KWC)[k] >> shift;                        \
            const float nsl_i = nslR[k];                                       \
            const float q_i   = qR[k];                                         \
            float s0 = (SRC.x > nsl_i) ? q_i * ERC.x : ER2C.x;                 \
            float s1 = (SRC.y > nsl_i) ? q_i * ERC.y : ER2C.y;                 \
            float s2 = (SRC.z > nsl_i) ? q_i * ERC.z : ER2C.z;                 \
            float s3 = (SRC.w > nsl_i) ? q_i * ERC.w : ER2C.w;                 \
            float w0 = (nib & 1u) ? s0 : 0.f;                                  \
            float w1 = (nib & 2u) ? s1 : 0.f;                                  \
            float w2 = (nib & 4u) ? s2 : 0.f;                                  \
            float w3 = (nib & 8u) ? s3 : 0.f;                                  \
            w0 = tf32r(w0); w1 = tf32r(w1); w2 = tf32r(w2); w3 = tf32r(w3);    \
            dpart[k] += (w0 + w1) + (w2 + w3);                                 \
            *(float4*)(bufW + (k * 16 + ii) * LDW) = make_float4(w0,w1,w2,w3); \
        }                                                                      \
    }                                                                          \
    __syncthreads();                                                           \
    /* prefetch next chunk's bits + factors (hidden behind MMA) */             \
    if ((JT) + 1 < 128) {                                                      \
        const int jn = j0 + 64;                                                \
        _Pragma("unroll")                                                      \
        for (int k = 0; k < 8; ++k)                                            \
            (KWN)[k] = keepB[k * 4096 + ((JT) + 1) * 2];                       \
        SRN  = *(const float4*)(srG  + jn + jj4 * 4);                          \
        ERN  = *(const float4*)(erG  + jn + jj4 * 4);                          \
        ER2N = *(const float4*)(er2G + jn + jj4 * 4);                          \
    }                                                                          \
    /* tensor-core accumulation */                                             \
    {                                                                          \
        const unsigned int aO = (BUF) ? (unsigned int)(WBUF * 4) : 0u;         \
        const unsigned int bO = (BUF) ? (unsigned int)(BBUF * 4) : 0u;         \
        _Pragma("unroll")                                                      \
        for (int kp = 0; kp < 4; ++kp) {                                       \
            unsigned int bf[4][4];                                             \
            _Pragma("unroll")                                                  \
            for (int nt = 0; nt < 4; ++nt) ldsm4(bf[nt], bAddr[nt] + bO + kp * 64); \
            _Pragma("unroll")                                                  \
            for (int sub = 0; sub < 2; ++sub) {                                \
                const int ks = kp * 2 + sub;                                   \
                unsigned int a0[4], a1[4];                                     \
                ldsm4(a0, aAddr0 + aO + ks * 32);                              \
                ldsm4(a1, aAddr1 + aO + ks * 32);                              \
                _Pragma("unroll")                                              \
                for (int nt = 0; nt < 4; ++nt) {                               \
                    mma_tf32(acc[0][nt], a0, bf[nt][2 * sub], bf[nt][2 * sub + 1]); \
                    mma_tf32(acc[1][nt], a1, bf[nt][2 * sub], bf[nt][2 * sub + 1]); \
                }                                                              \
            }                                                                  \
        }                                                                      \
    }                                                                          \
}

__global__ __launch_bounds__(256, 2) void k_gat(float* __restrict__ out) {
    extern __shared__ float sm[];
    float* denS = sm + OFF_DN;
    float* invD = sm + OFF_IV;

    const int tid  = threadIdx.x;
    const int lane = tid & 31;
    const int warp = tid >> 5;
    const int h    = blockIdx.x;
    const int i0   = blockIdx.y * 128;

    const int ii  = tid >> 4;       // 0..15
    const int jj4 = tid & 15;       // 0..15
    const unsigned int shift = (unsigned int)((jj4 & 7) * 4);

    // per-thread row factors (registers; only 2 per row after cancellation)
    float nslR[8], qR[8];
    #pragma unroll
    for (int k = 0; k < 8; ++k) {
        const int gi = h * NN + i0 + k * 16 + ii;
        nslR[k] = g_nsl[gi];
        qR  [k] = g_q  [gi];
    }

    // B staging mapping
    const int bn = tid >> 2;
    const int bq = tid & 3;
    const float* hp = g_hB + (size_t)(h * ND + bn) * NN;

    // mma mapping
    const int wm = warp >> 1;
    const int wn = warp & 1;
    unsigned int sbase = (unsigned int)__cvta_generic_to_shared(sm);
    const unsigned int aAddr0 = sbase + ((wm * 32 + (lane & 15)) * LDW + (lane >> 4) * 4) * 4;
    const unsigned int aAddr1 = aAddr0 + 16 * LDW * 4;
    unsigned int bAddr[4];
    #pragma unroll
    for (int nt = 0; nt < 4; ++nt)
        bAddr[nt] = sbase + OFF_BT * 4 +
                    ((wn * 32 + nt * 8 + (lane & 7)) * LDB + (lane >> 3) * 4) * 4;

    float acc[2][4][4];
    #pragma unroll
    for (int a = 0; a < 2; ++a)
        #pragma unroll
        for (int b = 0; b < 4; ++b)
            #pragma unroll
            for (int c = 0; c < 4; ++c) acc[a][b][c] = 0.f;
    float dpart[8] = {};

    const float* srG  = g_sr  + h * NN;
    const float* erG  = g_er  + h * NN;
    const float* er2G = g_er2 + h * NN;
    const unsigned int* keepB = g_keep + (size_t)(i0 + ii) * 256 + (jj4 >> 3);

    // prologue: prefetch chunk 0
    unsigned int kwA[8], kwB[8];
    float4 srA, erA, er2A, srB, erB, er2B;
    #pragma unroll
    for (int k = 0; k < 8; ++k) kwA[k] = keepB[k * 4096];
    srA  = *(const float4*)(srG  + jj4 * 4);
    erA  = *(const float4*)(erG  + jj4 * 4);
    er2A = *(const float4*)(er2G + jj4 * 4);

    for (int jt = 0; jt < 128; jt += 2) {
        CHUNK(jt,     0, kwA, srA, erA, er2A, kwB, srB, erB, er2B)
        CHUNK(jt + 1, 1, kwB, srB, erB, er2B, kwA, srA, erA, er2A)
    }

    // ---- denominators: 16-lane shuffle reduction ----
    #pragma unroll
    for (int k = 0; k < 8; ++k) {
        float v = dpart[k];
        v += __shfl_xor_sync(0xffffffffu, v, 1);
        v += __shfl_xor_sync(0xffffffffu, v, 2);
        v += __shfl_xor_sync(0xffffffffu, v, 4);
        v += __shfl_xor_sync(0xffffffffu, v, 8);
        if (jj4 == 0) denS[k * 16 + ii] = v;
    }
    __syncthreads();
    if (tid < 128) invD[tid] = 1.0f / denS[tid];
    __syncthreads();

    // ---- epilogue: normalize + store ----
    #pragma unroll
    for (int mt = 0; mt < 2; ++mt) {
        const int r0 = wm * 32 + mt * 16 + (lane >> 2);
        const float inv0 = invD[r0], inv1 = invD[r0 + 8];
        #pragma unroll
        for (int nt = 0; nt < 4; ++nt) {
            const int c = h * ND + wn * 32 + nt * 8 + (lane & 3) * 2;
            float2 v0 = make_float2(acc[mt][nt][0] * inv0, acc[mt][nt][1] * inv0);
            float2 v1 = make_float2(acc[mt][nt][2] * inv1, acc[mt][nt][3] * inv1);
            *(float2*)(out + (size_t)(i0 + r0)     * HD + c) = v0;
            *(float2*)(out + (size_t)(i0 + r0 + 8) * HD + c) = v1;
        }
    }
}

// ---------------- launch ----------------
extern "C" void kernel_launch(void* const* d_in, const int* in_sizes, int n_in,
                              void* d_out, int out_size) {
    const float* x   = (const float*)d_in[0];
    const int*   adj = (const int*)  d_in[1];
    const float* W   = (const float*)d_in[2];
    const float* a_l = (const float*)d_in[3];
    const float* a_r = (const float*)d_in[4];
    float* out = (float*)d_out;

    k_pack<<<2048, 256>>>(adj);
    k_proj<<<dim3(HD / 64, NN / 64), 256>>>(x, W);
    k_scores<<<NN / 256, 256>>>(a_l, a_r);

    cudaFuncSetAttribute(k_gat, cudaFuncAttributeMaxDynamicSharedMemorySize, SMEM_BYTES);
    k_gat<<<dim3(NH, NN / 128), 256, SMEM_BYTES>>>(out);
}

// round 7
// speedup vs baseline: 1.4364x; 1.1575x over previous
#include <cuda_runtime.h>
#include <math.h>
#include <stdint.h>

#define NN   8192
#define FIN  256
#define NH   4
#define ND   64
#define HD   256
#define LDB  68

// ---------------- device scratch (allocation-free contract) ----------------
__device__ float g_hT [NH * ND * NN];     // projected features, exact: [h][d][n]
__device__ float g_hB [NH * ND * NN];     // projected features, tf32-rounded
__device__ float g_nsl[NH * NN];          // -score_l
__device__ float g_q  [NH * NN];          // exp(0.8 * score_l)
__device__ float g_sr [NH * NN];
__device__ float g_er [NH * NN];
__device__ float g_er2[NH * NN];
__device__ unsigned int g_keep[NN * 256 + 512];   // keep bitmask, diag folded

// ---------------- helpers ----------------
__device__ __forceinline__ float tf32r(float x) {
    unsigned int u;
    asm("cvt.rna.tf32.f32 %0, %1;" : "=r"(u) : "f"(x));
    return __uint_as_float(u);
}
__device__ __forceinline__ void ldsm4(unsigned int* r, unsigned int addr) {
    asm volatile("ldmatrix.sync.aligned.m8n8.x4.shared.b16 {%0,%1,%2,%3}, [%4];"
                 : "=r"(r[0]), "=r"(r[1]), "=r"(r[2]), "=r"(r[3]) : "r"(addr));
}
__device__ __forceinline__ void mma_tf32(float* c, const unsigned int* a,
                                         unsigned int b0, unsigned int b1) {
    asm volatile("mma.sync.aligned.m16n8k8.row.col.f32.tf32.tf32.f32 "
                 "{%0,%1,%2,%3}, {%4,%5,%6,%7}, {%8,%9}, {%0,%1,%2,%3};"
                 : "+f"(c[0]), "+f"(c[1]), "+f"(c[2]), "+f"(c[3])
                 : "r"(a[0]), "r"(a[1]), "r"(a[2]), "r"(a[3]), "r"(b0), "r"(b1));
}

// ---------------- Kernel 1: g_hT/g_hB = (x @ W)^T ----------------
__global__ __launch_bounds__(256) void k_proj(const float* __restrict__ A,
                                              const float* __restrict__ B) {
    __shared__ float As[64 * 17];
    __shared__ float Bs[16 * 64];
    __shared__ float Tb[64 * 68];
    const int t  = threadIdx.x;
    const int ty = t >> 4, tx = t & 15;
    const int row0 = blockIdx.y * 64, col0 = blockIdx.x * 64;
    float acc[4][4] = {};
    for (int k0 = 0; k0 < FIN; k0 += 16) {
        #pragma unroll
        for (int l = 0; l < 4; ++l) {
            int idx = t + l * 256;
            int m = idx >> 4, k = idx & 15;
            As[m * 17 + k] = A[(size_t)(row0 + m) * FIN + k0 + k];
            int kb = idx >> 6, n = idx & 63;
            Bs[kb * 64 + n] = B[(size_t)(k0 + kb) * HD + col0 + n];
        }
        __syncthreads();
        #pragma unroll
        for (int k = 0; k < 16; ++k) {
            float a0 = As[(ty * 4 + 0) * 17 + k];
            float a1 = As[(ty * 4 + 1) * 17 + k];
            float a2 = As[(ty * 4 + 2) * 17 + k];
            float a3 = As[(ty * 4 + 3) * 17 + k];
            float4 b = *(const float4*)&Bs[k * 64 + tx * 4];
            acc[0][0] += a0 * b.x; acc[0][1] += a0 * b.y; acc[0][2] += a0 * b.z; acc[0][3] += a0 * b.w;
            acc[1][0] += a1 * b.x; acc[1][1] += a1 * b.y; acc[1][2] += a1 * b.z; acc[1][3] += a1 * b.w;
            acc[2][0] += a2 * b.x; acc[2][1] += a2 * b.y; acc[2][2] += a2 * b.z; acc[2][3] += a2 * b.w;
            acc[3][0] += a3 * b.x; acc[3][1] += a3 * b.y; acc[3][2] += a3 * b.z; acc[3][3] += a3 * b.w;
        }
        __syncthreads();
    }
    #pragma unroll
    for (int i = 0; i < 4; ++i)
        #pragma unroll
        for (int j = 0; j < 4; ++j)
            Tb[(tx * 4 + j) * 68 + (ty * 4 + i)] = acc[i][j];
    __syncthreads();
    const int c = t >> 2, q = t & 3;
    #pragma unroll
    for (int m = 0; m < 4; ++m) {
        float4 v = *(const float4*)&Tb[c * 68 + q * 16 + m * 4];
        size_t go = (size_t)(col0 + c) * NN + row0 + q * 16 + m * 4;
        *(float4*)(g_hT + go) = v;
        float4 r = make_float4(tf32r(v.x), tf32r(v.y), tf32r(v.z), tf32r(v.w));
        *(float4*)(g_hB + go) = r;
    }
}

// ---------------- Kernel 2: per-(node, head) scores + exp factors ----------------
__global__ __launch_bounds__(256) void k_scores(const float* __restrict__ a_l,
                                                const float* __restrict__ a_r) {
    __shared__ float alS[HD], arS[HD];
    const int t = threadIdx.x;
    if (t < HD) { alS[t] = a_l[t]; arS[t] = a_r[t]; }
    __syncthreads();
    const int n = blockIdx.x * 256 + t;
    #pragma unroll
    for (int h = 0; h < NH; ++h) {
        float sl = 0.f, sr = 0.f;
        #pragma unroll 8
        for (int d = 0; d < ND; ++d) {
            float v = g_hT[(size_t)(h * ND + d) * NN + n];
            sl += v * alS[h * ND + d];
            sr += v * arS[h * ND + d];
        }
        const int idx = h * NN + n;
        g_nsl[idx] = -sl;
        g_q  [idx] = expf(0.8f * sl);
        g_sr [idx] = sr;
        g_er [idx] = expf(sr);
        g_er2[idx] = expf(0.2f * sr);
    }
}

// ---------------- Kernel 2b: pack (adj + eye) != 0 into bitmask, MLP=8 ----------
__global__ __launch_bounds__(256) void k_pack(const int* __restrict__ adj) {
    const int lane = threadIdx.x & 31;
    const int gw   = (blockIdx.x * 256 + threadIdx.x) >> 5;
    const int nw   = (gridDim.x * 256) >> 5;
    for (int t = gw * 8; t < NN * 256; t += nw * 8) {
        const int* p = adj + (size_t)t * 32 + lane;
        int v[8];
        #pragma unroll
        for (int u = 0; u < 8; ++u) v[u] = p[u * 32];
        unsigned int b[8];
        #pragma unroll
        for (int u = 0; u < 8; ++u) b[u] = __ballot_sync(0xffffffffu, v[u] != 0);
        if (lane == 0) {
            #pragma unroll
            for (int u = 0; u < 8; ++u) {
                const int w = t + u, row = w >> 8, c = w & 255;
                if ((row >> 5) == c) b[u] |= 1u << (row & 31);
            }
            *(uint4*)(g_keep + t)     = make_uint4(b[0], b[1], b[2], b[3]);
            *(uint4*)(g_keep + t + 4) = make_uint4(b[4], b[5], b[6], b[7]);
        }
    }
}

// ---------------- Kernel 3: fused aggregation, A-fragments in registers --------
// block: 256 i-rows x 1 head. 8 warps = 8 M-groups (32 rows each), each warp
// covers all 64 N cols. A (attention weights) generated directly in mma fragment
// layout -> zero smem traffic for A. k-dim permuted (j = (kf&3)*16 + (kf>>2)) so
// each lane's 16 j-factors are contiguous. B tile staged with same permutation.
__global__ __launch_bounds__(256, 1) void k_gat(float* __restrict__ out) {
    __shared__ float Bt[2][64 * LDB];
    __shared__ float Fr[2][3][64];     // er, er2, sr per chunk

    const int tid  = threadIdx.x;
    const int lane = tid & 31;
    const int wm   = tid >> 5;
    const int h    = blockIdx.x;
    const int i0   = blockIdx.y * 256;
    const int q    = lane & 3;
    const int rl   = lane >> 2;

    // rows this lane generates weights for: t = m*2+p -> row wm*32 + m*16 + p*8 + rl
    float nslR[4], qR[4];
    int growL[4];
    #pragma unroll
    for (int t = 0; t < 4; ++t) {
        const int m = t >> 1, p = t & 1;
        growL[t] = i0 + wm * 32 + m * 16 + p * 8 + rl;
        nslR[t] = g_nsl[h * NN + growL[t]];
        qR[t]   = g_q  [h * NN + growL[t]];
    }
    const unsigned int shift = (unsigned int)((q & 1) * 16);

    // B staging mapping: thread (bn = feature d, bq = j-block); permuted store
    const int bn = tid >> 2, bq = tid & 3;
    const float* hp = g_hB + (size_t)(h * ND + bn) * NN;

    // factor staging: threads 0..47 (3 groups x 16)
    const int fgrp = tid >> 4, fidx = tid & 15;
    const float* fsrc = (fgrp == 0 ? g_er : (fgrp == 1 ? g_er2 : g_sr)) + h * NN;

    // ldsm B addresses (rows = feature n, cols = permuted k)
    const unsigned int sb0 = (unsigned int)__cvta_generic_to_shared(&Bt[0][0]);
    unsigned int bA[8];
    #pragma unroll
    for (int nt = 0; nt < 8; ++nt)
        bA[nt] = sb0 + (unsigned int)(((nt * 8 + (lane & 7)) * LDB + (lane >> 3) * 4) * 4);

    float acc[2][8][4];
    #pragma unroll
    for (int m = 0; m < 2; ++m)
        #pragma unroll
        for (int nt = 0; nt < 8; ++nt)
            #pragma unroll
            for (int c = 0; c < 4; ++c) acc[m][nt][c] = 0.f;
    float dpart[4] = {};

    // ---- prologue: keep words + stage chunk 0 ----
    unsigned int kwC[4];
    #pragma unroll
    for (int t = 0; t < 4; ++t)
        kwC[t] = g_keep[(size_t)growL[t] * 256 + (q >> 1)] >> shift;
    #pragma unroll
    for (int m4 = 0; m4 < 4; ++m4) {
        float4 v = *(const float4*)(hp + bq * 16 + m4 * 4);
        Bt[0][bn * LDB + 4 * (m4 * 4 + 0) + bq] = v.x;
        Bt[0][bn * LDB + 4 * (m4 * 4 + 1) + bq] = v.y;
        Bt[0][bn * LDB + 4 * (m4 * 4 + 2) + bq] = v.z;
        Bt[0][bn * LDB + 4 * (m4 * 4 + 3) + bq] = v.w;
    }
    if (tid < 48)
        *(float4*)&Fr[0][fgrp][fidx * 4] = *(const float4*)(fsrc + fidx * 4);
    __syncthreads();

    for (int jt = 0; jt < 128; ++jt) {
        const int buf = jt & 1;

        // ---- prefetch next chunk's inputs (consumed after the mma loop) ----
        unsigned int kwN[4];
        float4 bPre[4], fPre;
        if (jt < 127) {
            const int jn = (jt + 1) * 64;
            #pragma unroll
            for (int t = 0; t < 4; ++t)
                kwN[t] = g_keep[(size_t)growL[t] * 256 + (jt + 1) * 2 + (q >> 1)];
            #pragma unroll
            for (int m4 = 0; m4 < 4; ++m4)
                bPre[m4] = *(const float4*)(hp + jn + bq * 16 + m4 * 4);
            if (tid < 48) fPre = *(const float4*)(fsrc + jn + fidx * 4);
        }

        // ---- wgen (register fragments) + mma ----
        const unsigned int bufOff = buf ? (unsigned int)(64 * LDB * 4) : 0u;
        const float* erB  = Fr[buf][0];
        const float* er2B = Fr[buf][1];
        const float* srB  = Fr[buf][2];
        #pragma unroll
        for (int kp = 0; kp < 4; ++kp) {
            unsigned int bf[8][4];
            #pragma unroll
            for (int nt = 0; nt < 8; ++nt) ldsm4(bf[nt], bA[nt] + bufOff + kp * 64);
            const float4 er4  = *(const float4*)(erB  + q * 16 + kp * 4);
            const float4 er24 = *(const float4*)(er2B + q * 16 + kp * 4);
            const float4 sr4  = *(const float4*)(srB  + q * 16 + kp * 4);
            #pragma unroll
            for (int sub = 0; sub < 2; ++sub) {
                const int s = kp * 2 + sub;
                const float ex  = sub ? er4.z  : er4.x;
                const float ey  = sub ? er4.w  : er4.y;
                const float e2x = sub ? er24.z : er24.x;
                const float e2y = sub ? er24.w : er24.y;
                const float sx  = sub ? sr4.z  : sr4.x;
                const float sy  = sub ? sr4.w  : sr4.y;
                unsigned int a[2][4];
                #pragma unroll
                for (int m = 0; m < 2; ++m) {
                    #pragma unroll
                    for (int p = 0; p < 2; ++p) {
                        const int t = m * 2 + p;
                        const unsigned int bits = (kwC[t] >> (2 * s)) & 3u;
                        float w0 = (sx > nslR[t]) ? qR[t] * ex : e2x;
                        float w1 = (sy > nslR[t]) ? qR[t] * ey : e2y;
                        w0 = (bits & 1u) ? w0 : 0.f;
                        w1 = (bits & 2u) ? w1 : 0.f;
                        w0 = tf32r(w0); w1 = tf32r(w1);
                        dpart[t] += w0 + w1;
                        a[m][p]     = __float_as_uint(w0);
                        a[m][p + 2] = __float_as_uint(w1);
                    }
                }
                #pragma unroll
                for (int m = 0; m < 2; ++m)
                    #pragma unroll
                    for (int nt = 0; nt < 8; ++nt)
                        mma_tf32(acc[m][nt], a[m], bf[nt][2 * sub], bf[nt][2 * sub + 1]);
            }
        }

        // ---- commit prefetched data to the other buffer ----
        if (jt < 127) {
            const int nb = buf ^ 1;
            #pragma unroll
            for (int m4 = 0; m4 < 4; ++m4) {
                Bt[nb][bn * LDB + 4 * (m4 * 4 + 0) + bq] = bPre[m4].x;
                Bt[nb][bn * LDB + 4 * (m4 * 4 + 1) + bq] = bPre[m4].y;
                Bt[nb][bn * LDB + 4 * (m4 * 4 + 2) + bq] = bPre[m4].z;
                Bt[nb][bn * LDB + 4 * (m4 * 4 + 3) + bq] = bPre[m4].w;
            }
            if (tid < 48) *(float4*)&Fr[nb][fgrp][fidx * 4] = fPre;
            #pragma unroll
            for (int t = 0; t < 4; ++t) kwC[t] = kwN[t] >> shift;
        }
        __syncthreads();
    }

    // ---- denominators: 4-lane shuffle (lanes sharing rl cover all j) ----
    float inv[4];
    #pragma unroll
    for (int t = 0; t < 4; ++t) {
        float v = dpart[t];
        v += __shfl_xor_sync(0xffffffffu, v, 1);
        v += __shfl_xor_sync(0xffffffffu, v, 2);
        inv[t] = 1.0f / v;
    }

    // ---- epilogue: normalize + store ----
    #pragma unroll
    for (int m = 0; m < 2; ++m) {
        const int r0 = i0 + wm * 32 + m * 16 + rl;
        #pragma unroll
        for (int nt = 0; nt < 8; ++nt) {
            const int c = h * ND + nt * 8 + q * 2;
            float2 v0 = make_float2(acc[m][nt][0] * inv[2 * m],     acc[m][nt][1] * inv[2 * m]);
            float2 v1 = make_float2(acc[m][nt][2] * inv[2 * m + 1], acc[m][nt][3] * inv[2 * m + 1]);
            *(float2*)(out + (size_t)r0 * HD + c)       = v0;
            *(float2*)(out + (size_t)(r0 + 8) * HD + c) = v1;
        }
    }
}

// ---------------- launch ----------------
extern "C" void kernel_launch(void* const* d_in, const int* in_sizes, int n_in,
                              void* d_out, int out_size) {
    const float* x   = (const float*)d_in[0];
    const int*   adj = (const int*)  d_in[1];
    const float* W   = (const float*)d_in[2];
    const float* a_l = (const float*)d_in[3];
    const float* a_r = (const float*)d_in[4];
    float* out = (float*)d_out;

    k_pack<<<2048, 256>>>(adj);
    k_proj<<<dim3(HD / 64, NN / 64), 256>>>(x, W);
    k_scores<<<NN / 256, 256>>>(a_l, a_r);

    k_gat<<<dim3(NH, NN / 256), 256>>>(out);
}